// round 16
// baseline (speedup 1.0000x reference)
#include <cuda_runtime.h>
#include <math.h>
#include <stdint.h>

#define NB  8
#define SEQ 2048
#define DIM 512
#define SCALE 0.04419417382415922f  // 1/sqrt(512)

// Scratch: tf32-rounded Qr (pre-scaled), Kr, V transposed; exp-weights,
// per-(row, jtile) partial sums, and reciprocal row sums.
__device__ float g_Qr[(size_t)NB * SEQ * DIM];
__device__ float g_Kr[(size_t)NB * SEQ * DIM];
__device__ float g_Vt[(size_t)NB * DIM * SEQ];
__device__ float g_Ew[(size_t)NB * SEQ * SEQ];      // tf32(exp(logit))
__device__ float g_Ps[(size_t)NB * SEQ * 8];        // partial sums per j-tile
__device__ float g_Rs[(size_t)NB * SEQ];            // 1 / row sum

// ---------------------------------------------------------------------------
// helpers
// ---------------------------------------------------------------------------
__device__ __forceinline__ uint32_t f2tf(float x) {
    uint32_t u;
    asm("cvt.rna.tf32.f32 %0, %1;" : "=r"(u) : "f"(x));
    return u;
}
__device__ __forceinline__ float f2tf_f(float x) {
    return __uint_as_float(f2tf(x));
}

__device__ __forceinline__ uint32_t smem_u32(const void* p) {
    uint32_t a;
    asm("{ .reg .u64 t; cvta.to.shared.u64 t, %1; cvt.u32.u64 %0, t; }"
        : "=r"(a) : "l"(p));
    return a;
}

#define CP_ASYNC16(dst_u32, src_ptr) \
    asm volatile("cp.async.cg.shared.global [%0], [%1], 16;" \
                 :: "r"(dst_u32), "l"(src_ptr) : "memory")
#define CP_COMMIT() asm volatile("cp.async.commit_group;" ::: "memory")
#define CP_WAIT1()  asm volatile("cp.async.wait_group 1;" ::: "memory")

__device__ __forceinline__ void mma_tf32(float* d, const uint32_t* a, const uint32_t* b) {
    asm volatile(
        "mma.sync.aligned.m16n8k8.row.col.f32.tf32.tf32.f32 "
        "{%0,%1,%2,%3}, {%4,%5,%6,%7}, {%8,%9}, {%0,%1,%2,%3};\n"
        : "+f"(d[0]), "+f"(d[1]), "+f"(d[2]), "+f"(d[3])
        : "r"(a[0]), "r"(a[1]), "r"(a[2]), "r"(a[3]),
          "r"(b[0]), "r"(b[1]));
}

__device__ __forceinline__ void ldsm_x4(uint32_t* d, uint32_t addr) {
    asm volatile(
        "ldmatrix.sync.aligned.m8n8.x4.shared.b16 {%0,%1,%2,%3}, [%4];"
        : "=r"(d[0]), "=r"(d[1]), "=r"(d[2]), "=r"(d[3]) : "r"(addr));
}

// ---------------------------------------------------------------------------
// Pre-pass 1: tf32 round Q (pre-scaled by SCALE) and K.
// ---------------------------------------------------------------------------
__global__ __launch_bounds__(256)
void round_qk_kernel(const float* __restrict__ Q, const float* __restrict__ K,
                     float* __restrict__ Qr, float* __restrict__ Kr) {
    const int which = blockIdx.y;
    const float* in  = which ? K : Q;
    float*       out = which ? Kr : Qr;
    const float s = which ? 1.0f : SCALE;

    size_t i = (size_t)blockIdx.x * 256 + threadIdx.x;
    float4 v = reinterpret_cast<const float4*>(in)[i];
    v.x = f2tf_f(v.x * s); v.y = f2tf_f(v.y * s);
    v.z = f2tf_f(v.z * s); v.w = f2tf_f(v.w * s);
    reinterpret_cast<float4*>(out)[i] = v;
}

// ---------------------------------------------------------------------------
// Pre-pass 2: transpose V to [b][d][j] with tf32 rounding.
// ---------------------------------------------------------------------------
__global__ __launch_bounds__(256)
void transpose_v_kernel(const float* __restrict__ V, float* __restrict__ Vt) {
    __shared__ float t[32][33];
    const int b = blockIdx.z;
    const int j0 = blockIdx.x * 32;
    const int d0 = blockIdx.y * 32;
    const int tx = threadIdx.x, ty = threadIdx.y;  // 32 x 8
    const float* v = V + (size_t)b * SEQ * DIM;
    float* o = Vt + (size_t)b * DIM * SEQ;
#pragma unroll
    for (int i = 0; i < 4; i++)
        t[ty + i * 8][tx] = f2tf_f(v[(size_t)(j0 + ty + i * 8) * DIM + d0 + tx]);
    __syncthreads();
#pragma unroll
    for (int i = 0; i < 4; i++)
        o[(size_t)(d0 + ty + i * 8) * SEQ + j0 + tx] = t[tx][ty + i * 8];
}

// ---------------------------------------------------------------------------
// Unified NT GEMM: C[m,n] = sum_k A[m,k] * B[n,k]
// Block tile 128(m) x 256(n), BK=32, 3-stage cp.async, 256 threads
// (8 warps 2x4), warp tile 64x64, ldmatrix fragments (B paired x4).
// Stage layout (FIXED): A stage s at as_b + s*G_AW*4;
//                       B stage s at bs_b + s*G_BW*4.
// MODE 0 = qk (exp epilogue + partial sums), MODE 1 = av (row scale).
// ---------------------------------------------------------------------------
#define G_AW 4608   // A words per stage: 128*36
#define G_BW 9216   // B words per stage: 256*36

template <int KTOT, int LDA, int LDB, int LDC, int MODE>
__global__ __launch_bounds__(256)
void gemm_nt_kernel(const float* __restrict__ Ag, const float* __restrict__ Bg,
                    float* __restrict__ Cg, float* __restrict__ Ps,
                    const float* __restrict__ rs) {
    extern __shared__ __align__(16) uint32_t sh[];
    uint32_t* As = sh;                    // 3 stages of G_AW
    uint32_t* Bs = sh + 3 * G_AW;         // 3 stages of G_BW
    const uint32_t as_b = smem_u32(As);
    const uint32_t bs_b = smem_u32(Bs);

    const int z  = blockIdx.z;
    const int i0 = blockIdx.y * 128;
    const int n0 = blockIdx.x * 256;

    const float* a = Ag + (size_t)z * SEQ * LDA + (size_t)i0 * LDA;
    const float* bp = Bg + (size_t)z * (size_t)SEQ * DIM + (size_t)n0 * LDB;
    float* out = Cg + (size_t)z * SEQ * LDC;

    const int tid  = threadIdx.x;
    const int warp = tid >> 5;
    const int lane = tid & 31;
    const int wm = (warp & 1) * 64;       // 0,64
    const int wn = (warp >> 1) * 64;      // 0,64,128,192

    const int lr = lane & 7;
    const int g  = lane >> 3;
    // A x4: (row group +0,+8) x (k half 0,4)
    const uint32_t a_off = ((wm + (g & 1) * 8 + lr) * 36 + (g >> 1) * 4) * 4;
    // B paired x4: groups 0/1 = first n-tile of pair (k halves), 2/3 = second
    const uint32_t b_off = ((wn + (g >> 1) * 8 + lr) * 36 + (g & 1) * 4) * 4;

    const int r = lane >> 2;
    const int c = lane & 3;

    // gmem->smem: A 1024 f4 (4/thread), B 2048 f4 (8/thread)
    int arow[4], ac4[4];
#pragma unroll
    for (int t = 0; t < 4; t++) {
        int f = tid + t * 256;
        arow[t] = f >> 3;  ac4[t] = f & 7;
    }

    float acc[32][4];
#pragma unroll
    for (int i = 0; i < 32; i++)
#pragma unroll
        for (int j = 0; j < 4; j++) acc[i][j] = 0.0f;

    const int NT = KTOT / 32;

#pragma unroll
    for (int pc = 0; pc < 2; pc++) {
#pragma unroll
        for (int t = 0; t < 4; t++) {
            uint32_t so = (pc * G_AW + arow[t] * 36 + ac4[t] * 4) * 4;
            CP_ASYNC16(as_b + so, &a[(size_t)arow[t] * LDA + pc * 32 + ac4[t] * 4]);
        }
#pragma unroll
        for (int t = 0; t < 8; t++) {
            int f = tid + t * 256;
            int brow = f >> 3, bc4 = f & 7;
            uint32_t so = (pc * G_BW + brow * 36 + bc4 * 4) * 4;
            CP_ASYNC16(bs_b + so, &bp[(size_t)brow * LDB + pc * 32 + bc4 * 4]);
        }
        CP_COMMIT();
    }

    for (int kt = 0; kt < NT; kt++) {
        const int s = kt % 3;
        CP_WAIT1();
        __syncthreads();

        const uint32_t a_s = as_b + s * (G_AW * 4) + a_off;
        const uint32_t b_s = bs_b + s * (G_BW * 4) + b_off;

        {   // ks = 0 first: tensor pipe starts before next loads issue
            uint32_t au[4][4], bu[4][4];
#pragma unroll
            for (int mt = 0; mt < 4; mt++)
                ldsm_x4(au[mt], a_s + mt * 2304);
#pragma unroll
            for (int np = 0; np < 4; np++)
                ldsm_x4(bu[np], b_s + np * 2304);
#pragma unroll
            for (int mt = 0; mt < 4; mt++)
#pragma unroll
                for (int nt = 0; nt < 8; nt++)
                    mma_tf32(acc[mt * 8 + nt], au[mt], &bu[nt >> 1][(nt & 1) * 2]);
        }

        if (kt + 2 < NT) {
            const int s2 = (kt + 2) % 3;
            const int k0 = (kt + 2) * 32;
#pragma unroll
            for (int t = 0; t < 4; t++) {
                uint32_t so = (s2 * G_AW + arow[t] * 36 + ac4[t] * 4) * 4;
                CP_ASYNC16(as_b + so, &a[(size_t)arow[t] * LDA + k0 + ac4[t] * 4]);
            }
#pragma unroll
            for (int t = 0; t < 8; t++) {
                int f = tid + t * 256;
                int brow = f >> 3, bc4 = f & 7;
                uint32_t so = (s2 * G_BW + brow * 36 + bc4 * 4) * 4;
                CP_ASYNC16(bs_b + so, &bp[(size_t)brow * LDB + k0 + bc4 * 4]);
            }
        }
        CP_COMMIT();

#pragma unroll
        for (int ks = 1; ks < 4; ks++) {
            uint32_t au[4][4], bu[4][4];
#pragma unroll
            for (int mt = 0; mt < 4; mt++)
                ldsm_x4(au[mt], a_s + mt * 2304 + ks * 32);
#pragma unroll
            for (int np = 0; np < 4; np++)
                ldsm_x4(bu[np], b_s + np * 2304 + ks * 32);
#pragma unroll
            for (int mt = 0; mt < 4; mt++)
#pragma unroll
                for (int nt = 0; nt < 8; nt++)
                    mma_tf32(acc[mt * 8 + nt], au[mt], &bu[nt >> 1][(nt & 1) * 2]);
        }
    }

    if (MODE == 0) {
        // qk epilogue: e = tf32(exp(logit)); store + deterministic row sums.
        float sumL[4] = {0, 0, 0, 0}, sumH[4] = {0, 0, 0, 0};
#pragma unroll
        for (int mt = 0; mt < 4; mt++) {
#pragma unroll
            for (int nt = 0; nt < 8; nt++) {
                float* av = acc[mt * 8 + nt];
                float e0 = f2tf_f(__expf(av[0]));
                float e1 = f2tf_f(__expf(av[1]));
                float e2 = f2tf_f(__expf(av[2]));
                float e3 = f2tf_f(__expf(av[3]));
                sumL[mt] += e0 + e1;
                sumH[mt] += e2 + e3;
                int row = i0 + wm + mt * 16 + r;
                int col = n0 + wn + nt * 8 + c * 2;
                *reinterpret_cast<float2*>(&out[(size_t)row * LDC + col]) =
                    make_float2(e0, e1);
                *reinterpret_cast<float2*>(&out[(size_t)(row + 8) * LDC + col]) =
                    make_float2(e2, e3);
            }
        }
#pragma unroll
        for (int mt = 0; mt < 4; mt++) {
            sumL[mt] += __shfl_xor_sync(0xffffffffu, sumL[mt], 1);
            sumL[mt] += __shfl_xor_sync(0xffffffffu, sumL[mt], 2);
            sumH[mt] += __shfl_xor_sync(0xffffffffu, sumH[mt], 1);
            sumH[mt] += __shfl_xor_sync(0xffffffffu, sumH[mt], 2);
        }
        float* red = reinterpret_cast<float*>(sh);  // [4 n-groups][128 rows]
        __syncthreads();
        if (c == 0) {
#pragma unroll
            for (int mt = 0; mt < 4; mt++) {
                red[(warp >> 1) * 128 + wm + mt * 16 + r]     = sumL[mt];
                red[(warp >> 1) * 128 + wm + mt * 16 + r + 8] = sumH[mt];
            }
        }
        __syncthreads();
        if (tid < 128) {
            float tot = red[tid] + red[128 + tid] + red[256 + tid] + red[384 + tid];
            Ps[((size_t)z * SEQ + i0 + tid) * 8 + blockIdx.x] = tot;
        }
    } else {
        // av epilogue: scale each output row by rs[row].
#pragma unroll
        for (int mt = 0; mt < 4; mt++) {
            int row = i0 + wm + mt * 16 + r;
            float invL = rs[(size_t)z * SEQ + row];
            float invH = rs[(size_t)z * SEQ + row + 8];
#pragma unroll
            for (int nt = 0; nt < 8; nt++) {
                float* av = acc[mt * 8 + nt];
                int col = n0 + wn + nt * 8 + c * 2;
                *reinterpret_cast<float2*>(&out[(size_t)row * LDC + col]) =
                    make_float2(av[0] * invL, av[1] * invL);
                *reinterpret_cast<float2*>(&out[(size_t)(row + 8) * LDC + col]) =
                    make_float2(av[2] * invH, av[3] * invH);
            }
        }
    }
}

// ---------------------------------------------------------------------------
// Row sums: rs[row] = 1 / sum over 8 j-tile partials.
// ---------------------------------------------------------------------------
__global__ __launch_bounds__(256)
void rowsum_kernel(const float* __restrict__ Ps, float* __restrict__ rs) {
    int row = blockIdx.x * 256 + threadIdx.x;   // 16384 rows total
    const float* p = Ps + (size_t)row * 8;
    float s = 0.0f;
#pragma unroll
    for (int i = 0; i < 8; i++) s += p[i];
    rs[row] = 1.0f / s;
}

// ---------------------------------------------------------------------------
// Normalize: weights[i,j] = Ew[i,j] * rs[i]  (runs concurrent with av).
// ---------------------------------------------------------------------------
__global__ __launch_bounds__(256)
void normalize_kernel(const float* __restrict__ Ew, const float* __restrict__ rs,
                      float* __restrict__ w) {
    const int warp = threadIdx.x >> 5;
    const int lane = threadIdx.x & 31;
    const size_t row = (size_t)blockIdx.x * 8 + warp;
    const float4* in = reinterpret_cast<const float4*>(Ew + row * SEQ);
    float4* outp = reinterpret_cast<float4*>(w + row * SEQ);
    const float inv = rs[row];
#pragma unroll
    for (int i = 0; i < 16; i++) {
        float4 v = in[lane + 32 * i];
        v.x *= inv; v.y *= inv; v.z *= inv; v.w *= inv;
        outp[lane + 32 * i] = v;
    }
}

// ---------------------------------------------------------------------------
extern "C" void kernel_launch(void* const* d_in, const int* in_sizes, int n_in,
                              void* d_out, int out_size) {
    const float* Q = (const float*)d_in[0];
    const float* K = (const float*)d_in[1];
    const float* V = (const float*)d_in[2];

    float* ctx  = (float*)d_out;                      // [8, 2048, 512]
    float* attn = ctx + (size_t)NB * SEQ * DIM;       // [8, 2048, 2048]

    float *Qr, *Kr, *Vt, *Ew, *Ps, *Rs;
    cudaGetSymbolAddress((void**)&Qr, g_Qr);
    cudaGetSymbolAddress((void**)&Kr, g_Kr);
    cudaGetSymbolAddress((void**)&Vt, g_Vt);
    cudaGetSymbolAddress((void**)&Ew, g_Ew);
    cudaGetSymbolAddress((void**)&Ps, g_Ps);
    cudaGetSymbolAddress((void**)&Rs, g_Rs);

    constexpr int G_SMEM = 3 * (G_AW + G_BW) * 4;   // 165888 B
    cudaFuncSetAttribute(gemm_nt_kernel<DIM, DIM, DIM, SEQ, 0>,
                         cudaFuncAttributeMaxDynamicSharedMemorySize, G_SMEM);
    cudaFuncSetAttribute(gemm_nt_kernel<SEQ, SEQ, SEQ, DIM, 1>,
                         cudaFuncAttributeMaxDynamicSharedMemorySize, G_SMEM);

    static cudaStream_t s_side = nullptr;
    static cudaEvent_t s_fork = nullptr, s_vt = nullptr, s_sum = nullptr,
                       s_norm = nullptr;
    if (s_side == nullptr) {
        cudaStreamCreateWithFlags(&s_side, cudaStreamNonBlocking);
        cudaEventCreateWithFlags(&s_fork, cudaEventDisableTiming);
        cudaEventCreateWithFlags(&s_vt, cudaEventDisableTiming);
        cudaEventCreateWithFlags(&s_sum, cudaEventDisableTiming);
        cudaEventCreateWithFlags(&s_norm, cudaEventDisableTiming);
    }

    const int n4 = NB * SEQ * DIM / 4;

    // Fork side stream: V transpose (feeds av only).
    cudaEventRecord(s_fork, 0);
    cudaStreamWaitEvent(s_side, s_fork, 0);
    transpose_v_kernel<<<dim3(SEQ / 32, DIM / 32, NB), dim3(32, 8), 0, s_side>>>(V, Vt);
    cudaEventRecord(s_vt, s_side);

    // Main chain: round -> qk(+exp, partial sums) -> rowsum.
    round_qk_kernel<<<dim3(n4 / 256, 2), 256>>>(Q, K, Qr, Kr);

    dim3 g1(SEQ / 256, SEQ / 128, NB);
    gemm_nt_kernel<DIM, DIM, DIM, SEQ, 0><<<g1, 256, G_SMEM>>>(
        Qr, Kr, Ew, Ps, nullptr);

    rowsum_kernel<<<NB * SEQ / 256, 256>>>(Ps, Rs);
    cudaEventRecord(s_sum, 0);

    // Side: normalize weights output concurrent with av.
    cudaStreamWaitEvent(s_side, s_sum, 0);
    normalize_kernel<<<NB * SEQ / 8, 256, 0, s_side>>>(Ew, Rs, attn);
    cudaEventRecord(s_norm, s_side);

    // Main: av (needs Vt + Rs), then join normalize before graph end.
    cudaStreamWaitEvent(0, s_vt, 0);
    dim3 g2(DIM / 256, SEQ / 128, NB);
    gemm_nt_kernel<SEQ, SEQ, SEQ, DIM, 1><<<g2, 256, G_SMEM>>>(
        Ew, Vt, ctx, nullptr, Rs);
    cudaStreamWaitEvent(0, s_norm, 0);
}